// round 16
// baseline (speedup 1.0000x reference)
#include <cuda_runtime.h>

#define NQ 10
#define DEPTH 6
#define NF 1024
#define NC 10

typedef unsigned long long u64;

// Transition diagonals: T_l (l=1..5), 512 float4 each:
// entry [(l-1)*512 + r*32 + lane] = (re_lo, re_hi, im_lo, im_hi) for m = lane|(r<<5), halves = q9
// NOTE: T_1 is stored PRE-PERMUTED through ring-1's trailing shuffle (m ^= bit9(m)).
__device__ float4 g_diag[5 * 512];

// ---------- f32x2 packed helpers ----------
__device__ __forceinline__ u64 pk(float x, float y) {
    u64 u; asm("mov.b64 %0,{%1,%2};" : "=l"(u) : "f"(x), "f"(y)); return u;
}
__device__ __forceinline__ u64 dup2(float x) { return pk(x, x); }
__device__ __forceinline__ void unpk(u64 u, float& x, float& y) {
    asm("mov.b64 {%0,%1},%2;" : "=f"(x), "=f"(y) : "l"(u));
}
__device__ __forceinline__ u64 fma2(u64 a, u64 b, u64 c) {
    u64 d; asm("fma.rn.f32x2 %0,%1,%2,%3;" : "=l"(d) : "l"(a), "l"(b), "l"(c)); return d;
}
__device__ __forceinline__ u64 mul2(u64 a, u64 b) {
    u64 d; asm("mul.rn.f32x2 %0,%1,%2;" : "=l"(d) : "l"(a), "l"(b)); return d;
}
__device__ __forceinline__ u64 add2(u64 a, u64 b) {
    u64 d; asm("add.rn.f32x2 %0,%1,%2;" : "=l"(d) : "l"(a), "l"(b)); return d;
}
__device__ __forceinline__ u64 sub2(u64 a, u64 b) {
    u64 d; asm("sub.rn.f32x2 %0,%1,%2;" : "=l"(d) : "l"(a), "l"(b)); return d;
}
__device__ __forceinline__ u64 neg2(u64 a) { return a ^ 0x8000000080000000ULL; }
__device__ __forceinline__ u64 rot32(u64 v) { return (v >> 32) | (v << 32); }

#define LOMASK 0x00000000FFFFFFFFULL
#define HIMASK 0xFFFFFFFF00000000ULL
#define FULLM 0xffffffffu

__device__ __forceinline__ float lsgn(int lane, int mask, float v) {
    return (__popc(lane & mask) & 1) ? -v : v;
}

// ring source map sigma for ring range R: s ^= bit_i(s) << ((i+R)%10), i = 9..0
__device__ __forceinline__ int ring_sigma(int m, int R) {
    int s = m;
    for (int i = 9; i >= 0; i--) {
        int tt = i + R;
        if (tt >= 10) tt -= 10;
        s ^= ((s >> i) & 1) << tt;
    }
    return s;
}

// Prep kernel: build the 5 transition diagonals.
// T_1(m) = prod_q phiphase_{1,q}(bit_q(m)), PRE-PERMUTED: evaluated at m ^ bit9(m)
// T_l(m) = prod_q phiphase_{l,q}(bit_q(m)) * prod_q omegaphase_{l-1,q}(bit_q(sigma_l(m))), l>=2
__global__ void build_diag(const float* __restrict__ w) {
    int l = blockIdx.x + 1;   // 1..5
    int m = threadIdx.x;      // 0..511 (half = 0)
    float res[2], ims[2];
#pragma unroll
    for (int half = 0; half < 2; half++) {
        int mm = m | (half << 9);
        // For l==1, pre-permute through ring-1's trailing shuffle (flip lane bit 0 iff bit9)
        int mp = (l == 1) ? (mm ^ ((mm >> 9) & 1)) : mm;
        float dr = 1.f, di = 0.f;
        for (int q = 0; q < NQ; q++) {
            float a = 0.5f * w[(l * NQ + q) * 3 + 0];
            int b = (mp >> q) & 1;
            float cc, ss;
            sincosf(b ? a : -a, &ss, &cc);
            float nr = dr * cc - di * ss;
            float ni = dr * ss + di * cc;
            dr = nr; di = ni;
        }
        if (l >= 2) {
            int s = ring_sigma(mm, l);
            for (int q = 0; q < NQ; q++) {
                float a = 0.5f * w[((l - 1) * NQ + q) * 3 + 2];
                int b = (s >> q) & 1;
                float cc, ss;
                sincosf(b ? a : -a, &ss, &cc);
                float nr = dr * cc - di * ss;
                float ni = dr * ss + di * cc;
                dr = nr; di = ni;
            }
        }
        res[half] = dr; ims[half] = di;
    }
    g_diag[(l - 1) * 512 + m] = make_float4(res[0], res[1], ims[0], ims[1]);
}

// Amplitude index m: bits0-4 = lane, bits5-8 = reg r (0..15), bit9 = u64 half.
template <int R>
__device__ __forceinline__ unsigned ring_mlo(int r) {
    unsigned m = 0;
#pragma unroll
    for (int c = 5; c <= 8; c++)
        if (c + R >= 10 && ((r >> (c - 5)) & 1)) m |= 1u << (c + R - 10);
    return m;
}

template <int R>
__device__ __forceinline__ void cnot_layer(u64 (&sr)[16], u64 (&si)[16], int lane) {
    constexpr int K = 5 - R;
    if (K > 0) {
        int src = lane;
#pragma unroll
        for (int i = K - 1; i >= 0; i--) src ^= ((src >> i) & 1) << (i + R);
#pragma unroll
        for (int r = 0; r < 16; r++) {
            sr[r] = __shfl_sync(FULLM, sr[r], src);
            si[r] = __shfl_sync(FULLM, si[r], src);
        }
    }
#pragma unroll
    for (int c = K; c < 5; c++) {
        const int t = c + R;
        if (t < 9) {
            const int tb = 1 << (t - 5);
            bool ctrl = (lane >> c) & 1;
#pragma unroll
            for (int r0 = 0; r0 < 16; r0++)
                if (!(r0 & tb)) {
                    const int r1 = r0 | tb;
                    u64 t0 = sr[r0], t1 = si[r0];
                    sr[r0] = ctrl ? sr[r1] : sr[r0];
                    si[r0] = ctrl ? si[r1] : si[r0];
                    sr[r1] = ctrl ? t0 : sr[r1];
                    si[r1] = ctrl ? t1 : si[r1];
                }
        } else {  // t == 9
            bool ctrl = (lane >> c) & 1;
#pragma unroll
            for (int r = 0; r < 16; r++) {
                u64 rr = rot32(sr[r]), ri = rot32(si[r]);
                sr[r] = ctrl ? rr : sr[r];
                si[r] = ctrl ? ri : si[r];
            }
        }
    }
#pragma unroll
    for (int c = 5; c <= 8; c++) {
        const int t = c + R;
        if (t <= 8) {
            const int cb = 1 << (c - 5), tb = 1 << (t - 5);
#pragma unroll
            for (int r0 = 0; r0 < 16; r0++)
                if ((r0 & cb) && !(r0 & tb)) {
                    const int r1 = r0 | tb;
                    u64 tmp = sr[r0]; sr[r0] = sr[r1]; sr[r1] = tmp;
                    tmp = si[r0]; si[r0] = si[r1]; si[r1] = tmp;
                }
        } else if (t == 9) {
            const int cb = 1 << (c - 5);
#pragma unroll
            for (int r = 0; r < 16; r++)
                if (r & cb) {
                    sr[r] = rot32(sr[r]);
                    si[r] = rot32(si[r]);
                }
        }
    }
#pragma unroll
    for (int r = 0; r < 16; r++) {
        const unsigned mlo = ring_mlo<R>(r);
        const unsigned mhi = mlo ^ (1u << (R - 1));
        {
            unsigned lo = (unsigned)sr[r], hi = (unsigned)(sr[r] >> 32);
            if (mlo) lo = __shfl_xor_sync(FULLM, lo, mlo);
            hi = __shfl_xor_sync(FULLM, hi, mhi);
            sr[r] = (u64)lo | ((u64)hi << 32);
        }
        {
            unsigned lo = (unsigned)si[r], hi = (unsigned)(si[r] >> 32);
            if (mlo) lo = __shfl_xor_sync(FULLM, lo, mlo);
            hi = __shfl_xor_sync(FULLM, hi, mhi);
            si[r] = (u64)lo | ((u64)hi << 32);
        }
    }
}

// Ring 1 WITHOUT its trailing shuffle (that shuffle is fused into layer 1's q0 gate).
__device__ __forceinline__ void cnot_ring1_notail(u64 (&sr)[16], u64 (&si)[16], int lane) {
    // leading composed shuffle: c = 0..3 (lane ctrl -> lane target t=c+1)
    int src = lane;
#pragma unroll
    for (int i = 3; i >= 0; i--) src ^= ((src >> i) & 1) << (i + 1);
#pragma unroll
    for (int r = 0; r < 16; r++) {
        sr[r] = __shfl_sync(FULLM, sr[r], src);
        si[r] = __shfl_sync(FULLM, si[r], src);
    }
    // c=4 -> t=5: lane ctrl / reg target
    {
        bool ctrl = (lane >> 4) & 1;
#pragma unroll
        for (int r0 = 0; r0 < 16; r0++)
            if (!(r0 & 1)) {
                const int r1 = r0 | 1;
                u64 t0 = sr[r0], t1 = si[r0];
                sr[r0] = ctrl ? sr[r1] : sr[r0];
                si[r0] = ctrl ? si[r1] : si[r0];
                sr[r1] = ctrl ? t0 : sr[r1];
                si[r1] = ctrl ? t1 : si[r1];
            }
    }
    // c=5..7 -> t=6..8: reg/reg renames
#pragma unroll
    for (int c = 5; c <= 7; c++) {
        const int cb = 1 << (c - 5), tb = 1 << (c - 4);
#pragma unroll
        for (int r0 = 0; r0 < 16; r0++)
            if ((r0 & cb) && !(r0 & tb)) {
                const int r1 = r0 | tb;
                u64 tmp = sr[r0]; sr[r0] = sr[r1]; sr[r1] = tmp;
                tmp = si[r0]; si[r0] = si[r1]; si[r1] = tmp;
            }
    }
    // c=8 -> t=9: reg ctrl / half target
#pragma unroll
    for (int r = 0; r < 16; r++)
        if (r & 8) {
            sr[r] = rot32(sr[r]);
            si[r] = rot32(si[r]);
        }
    // c=9 -> t=0 trailing (hi-word shfl by 1) deliberately OMITTED (fused into q0 gate)
}

__global__ __launch_bounds__(128, 5) void fused_kernel(
    const float* __restrict__ x, const float* __restrict__ Wp,
    const float* __restrict__ w, const float* __restrict__ Wout,
    const float* __restrict__ bout, float* __restrict__ out, int B) {
    // layer-0 full SU(2) gates + RY(theta) coefficients for layers 1..5
    __shared__ float4 rot0[NQ];
    __shared__ float2 sry[5 * NQ];
    const int tid = threadIdx.x;
    if (tid < DEPTH * NQ) {
        float theta = w[tid * 3 + 1];
        float c, s;
        sincosf(0.5f * theta, &s, &c);
        if (tid < NQ) {
            float phi = w[tid * 3 + 0], omega = w[tid * 3 + 2];
            float sp, cp, sm, cm;
            sincosf(-0.5f * (phi + omega), &sp, &cp);
            sincosf(-0.5f * (phi - omega), &sm, &cm);
            rot0[tid] = make_float4(cp * c, sp * c, -cm * s, sm * s);
        } else {
            sry[tid - NQ] = make_float2(c, s);
        }
    }
    __syncthreads();

    const int warp = tid >> 5, lane = tid & 31;
    const int b = blockIdx.x * 4 + warp;
    if (b >= B) return;

    // ---- projection -> per-lane half-angle trig ----
    float myc = 0.f, mys = 0.f;
    {
        const float4* xv = (const float4*)(x + (size_t)b * NF);
        float acc[NQ];
#pragma unroll
        for (int q = 0; q < NQ; q++) acc[q] = 0.f;
#pragma unroll
        for (int it = 0; it < 8; it++) {
            float4 xx = xv[it * 32 + lane];
#pragma unroll
            for (int q = 0; q < NQ; q++) {
                float4 ww = __ldg(&((const float4*)(Wp + q * NF))[it * 32 + lane]);
                acc[q] += xx.x * ww.x + xx.y * ww.y + xx.z * ww.z + xx.w * ww.w;
            }
        }
#pragma unroll
        for (int off = 16; off > 0; off >>= 1)
#pragma unroll
            for (int q = 0; q < NQ; q++) acc[q] += __shfl_xor_sync(FULLM, acc[q], off);
        if (lane < NQ) {
            float v = acc[0];
#pragma unroll
            for (int q = 1; q < NQ; q++)
                if (lane == q) v = acc[q];
            float half = tanhf(v) * 0.78539816339744831f;
            sincosf(half, &mys, &myc);
        }
    }

    // ---- init: RY product state with FULL layer-0 Rot folded in ----
    float plr, pli;
    {
        plr = 1.f; pli = 0.f;
#pragma unroll
        for (int q = 0; q < 5; q++) {
            float cq = __shfl_sync(FULLM, myc, q);
            float sq = __shfl_sync(FULLM, mys, q);
            float4 G = rot0[q];
            bool bq = (lane >> q) & 1;
            float wr = bq ? (-G.z * cq + G.x * sq) : (G.x * cq + G.z * sq);
            float wi = bq ? (G.w * cq - G.y * sq) : (G.y * cq + G.w * sq);
            float nr = plr * wr - pli * wi;
            float ni = plr * wi + pli * wr;
            plr = nr; pli = ni;
        }
    }
    u64 sr[16], si[16];
    {
        float ar2[4], ai2[4], br2[4], bi2[4];
        {
            float c5 = __shfl_sync(FULLM, myc, 5), s5 = __shfl_sync(FULLM, mys, 5);
            float c6 = __shfl_sync(FULLM, myc, 6), s6 = __shfl_sync(FULLM, mys, 6);
            float c7 = __shfl_sync(FULLM, myc, 7), s7 = __shfl_sync(FULLM, mys, 7);
            float c8 = __shfl_sync(FULLM, myc, 8), s8 = __shfl_sync(FULLM, mys, 8);
            float4 G5 = rot0[5], G6 = rot0[6], G7 = rot0[7], G8 = rot0[8];
            float v5r[2], v5i[2], v6r[2], v6i[2], v7r[2], v7i[2], v8r[2], v8i[2];
            v5r[0] = G5.x * c5 + G5.z * s5; v5i[0] = G5.y * c5 + G5.w * s5;
            v5r[1] = -G5.z * c5 + G5.x * s5; v5i[1] = G5.w * c5 - G5.y * s5;
            v6r[0] = G6.x * c6 + G6.z * s6; v6i[0] = G6.y * c6 + G6.w * s6;
            v6r[1] = -G6.z * c6 + G6.x * s6; v6i[1] = G6.w * c6 - G6.y * s6;
            v7r[0] = G7.x * c7 + G7.z * s7; v7i[0] = G7.y * c7 + G7.w * s7;
            v7r[1] = -G7.z * c7 + G7.x * s7; v7i[1] = G7.w * c7 - G7.y * s7;
            v8r[0] = G8.x * c8 + G8.z * s8; v8i[0] = G8.y * c8 + G8.w * s8;
            v8r[1] = -G8.z * c8 + G8.x * s8; v8i[1] = G8.w * c8 - G8.y * s8;
#pragma unroll
            for (int k = 0; k < 4; k++) {
                int b5 = k & 1, b6 = (k >> 1) & 1;
                ar2[k] = v5r[b5] * v6r[b6] - v5i[b5] * v6i[b6];
                ai2[k] = v5r[b5] * v6i[b6] + v5i[b5] * v6r[b6];
                br2[k] = v7r[b5] * v8r[b6] - v7i[b5] * v8i[b6];
                bi2[k] = v7r[b5] * v8i[b6] + v7i[b5] * v8r[b6];
            }
        }
        float c9 = __shfl_sync(FULLM, myc, 9), s9 = __shfl_sync(FULLM, mys, 9);
        float4 G9 = rot0[9];
        u64 V9r = pk(G9.x * c9 + G9.z * s9, -G9.z * c9 + G9.x * s9);
        u64 V9i = pk(G9.y * c9 + G9.w * s9, G9.w * c9 - G9.y * s9);
#pragma unroll
        for (int r = 0; r < 16; r++) {
            float lr = ar2[r & 3], li = ai2[r & 3];
            float hr = br2[r >> 2], hi = bi2[r >> 2];
            float rpr = lr * hr - li * hi;
            float rpi = lr * hi + li * hr;
            float baser = plr * rpr - pli * rpi;
            float basei = plr * rpi + pli * rpr;
            u64 br_ = dup2(baser), bi_ = dup2(basei);
            sr[r] = fma2(br_, V9r, mul2(neg2(bi_), V9i));
            si[r] = fma2(br_, V9i, mul2(bi_, V9r));
        }
    }

    // ---- ring 1 (no trailing), permuted diag T'_1, fused trailing+q0, rest of layer 1 ----
    cnot_ring1_notail(sr, si, lane);
    {
        // permuted transition diagonal T'_1
        const float4* dtab = &g_diag[0];
#pragma unroll
        for (int r = 0; r < 16; r++) {
            float4 d = __ldg(&dtab[r * 32 + lane]);
            u64 drk = pk(d.x, d.y), dik = pk(d.z, d.w);
            u64 mr = sr[r], mi = si[r];
            sr[r] = sub2(mul2(drk, mr), mul2(dik, mi));
            si[r] = fma2(drk, mi, mul2(dik, mr));
        }
        // fused ring-1 trailing shuffle + RY lane gate q0
        {
            float2 cs = sry[0];  // layer 1, q0
            bool hb = lane & 1;
            u64 C = dup2(cs.x), S = dup2(hb ? cs.y : -cs.y);
#pragma unroll
            for (int r = 0; r < 16; r++) {
                {
                    unsigned lo = (unsigned)sr[r], hi = (unsigned)(sr[r] >> 32);
                    unsigned self_hi = __shfl_xor_sync(FULLM, hi, 1);
                    unsigned part_lo = __shfl_xor_sync(FULLM, lo, 1);
                    u64 self = (u64)lo | ((u64)self_hi << 32);
                    u64 part = (u64)part_lo | ((u64)hi << 32);
                    sr[r] = fma2(C, self, mul2(S, part));
                }
                {
                    unsigned lo = (unsigned)si[r], hi = (unsigned)(si[r] >> 32);
                    unsigned self_hi = __shfl_xor_sync(FULLM, hi, 1);
                    unsigned part_lo = __shfl_xor_sync(FULLM, lo, 1);
                    u64 self = (u64)lo | ((u64)self_hi << 32);
                    u64 part = (u64)part_lo | ((u64)hi << 32);
                    si[r] = fma2(C, self, mul2(S, part));
                }
            }
        }
        // remaining lane gates q1..q4
#pragma unroll
        for (int q = 1; q < 5; q++) {
            float2 cs = sry[q];
            bool hb = (lane >> q) & 1;
            u64 C = dup2(cs.x), S = dup2(hb ? cs.y : -cs.y);
#pragma unroll
            for (int r = 0; r < 16; r++) {
                u64 pr_ = __shfl_xor_sync(FULLM, sr[r], 1 << q);
                u64 pi_ = __shfl_xor_sync(FULLM, si[r], 1 << q);
                sr[r] = fma2(C, sr[r], mul2(S, pr_));
                si[r] = fma2(C, si[r], mul2(S, pi_));
            }
        }
        // reg gates q5..q8
#pragma unroll
        for (int q = 5; q < 9; q++) {
            float2 cs = sry[q];
            u64 C = dup2(cs.x), S = dup2(cs.y), Sn = dup2(-cs.y);
            const int jb = 1 << (q - 5);
#pragma unroll
            for (int r0 = 0; r0 < 16; r0++)
                if (!(r0 & jb)) {
                    const int r1 = r0 | jb;
                    u64 a0r = sr[r0], a0i = si[r0];
                    u64 a1r = sr[r1], a1i = si[r1];
                    sr[r0] = fma2(C, a0r, mul2(Sn, a1r));
                    si[r0] = fma2(C, a0i, mul2(Sn, a1i));
                    sr[r1] = fma2(C, a1r, mul2(S, a0r));
                    si[r1] = fma2(C, a1i, mul2(S, a0i));
                }
        }
        // half gate q9
        {
            float2 cs = sry[9];
            u64 C = dup2(cs.x), Spk = pk(-cs.y, cs.y);
#pragma unroll
            for (int r = 0; r < 16; r++) {
                u64 tr = rot32(sr[r]), ti = rot32(si[r]);
                sr[r] = fma2(C, sr[r], mul2(Spk, tr));
                si[r] = fma2(C, si[r], mul2(Spk, ti));
            }
        }
    }
    cnot_layer<2>(sr, si, lane);

    // ---- layers 2..5 (round-14 structure; layer 5's R=6 ring folded into expvals) ----
#pragma unroll 1
    for (int l = 2; l < DEPTH; l++) {
        {
            const float4* dtab = &g_diag[(l - 1) * 512];
#pragma unroll
            for (int r = 0; r < 16; r++) {
                float4 d = __ldg(&dtab[r * 32 + lane]);
                u64 drk = pk(d.x, d.y), dik = pk(d.z, d.w);
                u64 mr = sr[r], mi = si[r];
                sr[r] = sub2(mul2(drk, mr), mul2(dik, mi));
                si[r] = fma2(drk, mi, mul2(dik, mr));
            }
        }
#pragma unroll
        for (int q = 0; q < 5; q++) {
            float2 cs = sry[(l - 1) * NQ + q];
            bool hb = (lane >> q) & 1;
            u64 C = dup2(cs.x), S = dup2(hb ? cs.y : -cs.y);
#pragma unroll
            for (int r = 0; r < 16; r++) {
                u64 pr_ = __shfl_xor_sync(FULLM, sr[r], 1 << q);
                u64 pi_ = __shfl_xor_sync(FULLM, si[r], 1 << q);
                sr[r] = fma2(C, sr[r], mul2(S, pr_));
                si[r] = fma2(C, si[r], mul2(S, pi_));
            }
        }
#pragma unroll
        for (int q = 5; q < 9; q++) {
            float2 cs = sry[(l - 1) * NQ + q];
            u64 C = dup2(cs.x), S = dup2(cs.y), Sn = dup2(-cs.y);
            const int jb = 1 << (q - 5);
#pragma unroll
            for (int r0 = 0; r0 < 16; r0++)
                if (!(r0 & jb)) {
                    const int r1 = r0 | jb;
                    u64 a0r = sr[r0], a0i = si[r0];
                    u64 a1r = sr[r1], a1i = si[r1];
                    sr[r0] = fma2(C, a0r, mul2(Sn, a1r));
                    si[r0] = fma2(C, a0i, mul2(Sn, a1i));
                    sr[r1] = fma2(C, a1r, mul2(S, a0r));
                    si[r1] = fma2(C, a1i, mul2(S, a0i));
                }
        }
        {
            float2 cs = sry[(l - 1) * NQ + 9];
            u64 C = dup2(cs.x), Spk = pk(-cs.y, cs.y);
#pragma unroll
            for (int r = 0; r < 16; r++) {
                u64 tr = rot32(sr[r]), ti = rot32(si[r]);
                sr[r] = fma2(C, sr[r], mul2(Spk, tr));
                si[r] = fma2(C, si[r], mul2(Spk, ti));
            }
        }
        switch (l) {
            case 2: cnot_layer<3>(sr, si, lane); break;
            case 3: cnot_layer<4>(sr, si, lane); break;
            case 4: cnot_layer<5>(sr, si, lane); break;
            default: break;
        }
    }

    // ---- Z expvals with R=6 ring folded in as GF(2) parity masks ----
    u64 A0 = 0ULL, A1 = 0ULL, A2 = 0ULL, A4 = 0ULL, A8 = 0ULL;
#pragma unroll
    for (int r = 0; r < 16; r++) {
        u64 p = fma2(sr[r], sr[r], mul2(si[r], si[r]));
        A0 = add2(A0, p);
        A1 = (r & 1) ? sub2(A1, p) : add2(A1, p);
        A2 = (r & 2) ? sub2(A2, p) : add2(A2, p);
        A4 = (r & 4) ? sub2(A4, p) : add2(A4, p);
        A8 = (r & 8) ? sub2(A8, p) : add2(A8, p);
    }
    u64 E[5];
    {
        float lo, hi;
        float e0, e1, e2, e3, e4, e5, e6, e7, e8, e9;
        unpk(A0, lo, hi);
        e0 = lsgn(lane, 0x11, lo + hi);
        e9 = lsgn(lane, 0x08, lo - hi);
        unpk(A1, lo, hi);
        e1 = lsgn(lane, 0x02, lo + hi);
        e5 = lsgn(lane, 0x08, lo - hi);
        unpk(A2, lo, hi);
        e2 = lsgn(lane, 0x05, lo + hi);
        e6 = lsgn(lane, 0x01, lo + hi);
        unpk(A4, lo, hi);
        e3 = lsgn(lane, 0x0A, lo + hi);
        e7 = lsgn(lane, 0x02, lo + hi);
        unpk(A8, lo, hi);
        e4 = lsgn(lane, 0x14, lo + hi);
        e8 = lsgn(lane, 0x04, lo + hi);
        E[0] = pk(e0, e1); E[1] = pk(e2, e3); E[2] = pk(e4, e5);
        E[3] = pk(e6, e7); E[4] = pk(e8, e9);
    }
#pragma unroll
    for (int off = 16; off > 0; off >>= 1)
#pragma unroll
        for (int k = 0; k < 5; k++)
            E[k] = add2(E[k], __shfl_xor_sync(FULLM, E[k], off));

    // ---- linear head ----
    if (lane < NC) {
        float e[NQ];
#pragma unroll
        for (int k = 0; k < 5; k++) unpk(E[k], e[2 * k], e[2 * k + 1]);
        float o = __ldg(&bout[lane]);
#pragma unroll
        for (int q = 0; q < NQ; q++) o += e[q] * __ldg(&Wout[lane * NQ + q]);
        out[(size_t)b * NC + lane] = o;
    }
}

extern "C" void kernel_launch(void* const* d_in, const int* in_sizes, int n_in,
                              void* d_out, int out_size) {
    const float* x = (const float*)d_in[0];
    const float* W_proj = (const float*)d_in[1];
    const float* weights = (const float*)d_in[2];
    const float* W_out = (const float*)d_in[3];
    const float* b_out = (const float*)d_in[4];
    float* out = (float*)d_out;

    int B = in_sizes[0] / NF;
    int nblk = (B + 3) / 4;

    build_diag<<<5, 512>>>(weights);
    fused_kernel<<<nblk, 128>>>(x, W_proj, weights, W_out, b_out, out, B);
}

// round 17
// speedup vs baseline: 1.0556x; 1.0556x over previous
#include <cuda_runtime.h>

#define NQ 10
#define DEPTH 6
#define NF 1024
#define NC 10

typedef unsigned long long u64;

// Transition diagonals: T_l (l=1..5), 512 float4 each:
// entry [(l-1)*512 + r*32 + lane] = (re_lo, re_hi, im_lo, im_hi) for m = lane|(r<<5), halves = q9
__device__ float4 g_diag[5 * 512];

// ---------- f32x2 packed helpers ----------
__device__ __forceinline__ u64 pk(float x, float y) {
    u64 u; asm("mov.b64 %0,{%1,%2};" : "=l"(u) : "f"(x), "f"(y)); return u;
}
__device__ __forceinline__ u64 dup2(float x) { return pk(x, x); }
__device__ __forceinline__ void unpk(u64 u, float& x, float& y) {
    asm("mov.b64 {%0,%1},%2;" : "=f"(x), "=f"(y) : "l"(u));
}
__device__ __forceinline__ u64 fma2(u64 a, u64 b, u64 c) {
    u64 d; asm("fma.rn.f32x2 %0,%1,%2,%3;" : "=l"(d) : "l"(a), "l"(b), "l"(c)); return d;
}
__device__ __forceinline__ u64 mul2(u64 a, u64 b) {
    u64 d; asm("mul.rn.f32x2 %0,%1,%2;" : "=l"(d) : "l"(a), "l"(b)); return d;
}
__device__ __forceinline__ u64 add2(u64 a, u64 b) {
    u64 d; asm("add.rn.f32x2 %0,%1,%2;" : "=l"(d) : "l"(a), "l"(b)); return d;
}
__device__ __forceinline__ u64 sub2(u64 a, u64 b) {
    u64 d; asm("sub.rn.f32x2 %0,%1,%2;" : "=l"(d) : "l"(a), "l"(b)); return d;
}
__device__ __forceinline__ u64 neg2(u64 a) { return a ^ 0x8000000080000000ULL; }
__device__ __forceinline__ u64 rot32(u64 v) { return (v >> 32) | (v << 32); }

#define LOMASK 0x00000000FFFFFFFFULL
#define HIMASK 0xFFFFFFFF00000000ULL
#define FULLM 0xffffffffu

__device__ __forceinline__ float lsgn(int lane, int mask, float v) {
    return (__popc(lane & mask) & 1) ? -v : v;
}

// ring source map sigma for ring range R: s ^= bit_i(s) << ((i+R)%10), i = 9..0
__device__ __forceinline__ int ring_sigma(int m, int R) {
    int s = m;
    for (int i = 9; i >= 0; i--) {
        int tt = i + R;
        if (tt >= 10) tt -= 10;
        s ^= ((s >> i) & 1) << tt;
    }
    return s;
}

// Prep kernel (angle-sum form): phases multiply <=> angles add, so the diagonal
// entry is exp(i * [ sum_q ±phi_{l,q}/2  +  sum_q ±omega_{l-1,q}/2 (at sigma_l(m)) ])
// -> 20 signed adds + ONE sincosf per (m, half) instead of 40 sincosf + 40 cmuls.
__global__ void build_diag(const float* __restrict__ w) {
    int l = blockIdx.x + 1;   // 1..5
    int m = threadIdx.x;      // 0..511
    float res[2], ims[2];
#pragma unroll
    for (int half = 0; half < 2; half++) {
        int mm = m | (half << 9);
        float ang = 0.f;
        for (int q = 0; q < NQ; q++) {
            float a = 0.5f * w[(l * NQ + q) * 3 + 0];
            ang += ((mm >> q) & 1) ? a : -a;
        }
        if (l >= 2) {
            int s = ring_sigma(mm, l);
            for (int q = 0; q < NQ; q++) {
                float a = 0.5f * w[((l - 1) * NQ + q) * 3 + 2];
                ang += ((s >> q) & 1) ? a : -a;
            }
        }
        sincosf(ang, &ims[half], &res[half]);
    }
    g_diag[(l - 1) * 512 + m] = make_float4(res[0], res[1], ims[0], ims[1]);
}

// Amplitude index m: bits0-4 = lane, bits5-8 = reg r (0..15), bit9 = u64 half.
template <int R>
__device__ __forceinline__ unsigned ring_mlo(int r) {
    unsigned m = 0;
#pragma unroll
    for (int c = 5; c <= 8; c++)
        if (c + R >= 10 && ((r >> (c - 5)) & 1)) m |= 1u << (c + R - 10);
    return m;
}

template <int R>
__device__ __forceinline__ void cnot_layer(u64 (&sr)[16], u64 (&si)[16], int lane) {
    constexpr int K = 5 - R;
    if (K > 0) {
        int src = lane;
#pragma unroll
        for (int i = K - 1; i >= 0; i--) src ^= ((src >> i) & 1) << (i + R);
#pragma unroll
        for (int r = 0; r < 16; r++) {
            sr[r] = __shfl_sync(FULLM, sr[r], src);
            si[r] = __shfl_sync(FULLM, si[r], src);
        }
    }
#pragma unroll
    for (int c = K; c < 5; c++) {
        const int t = c + R;
        if (t < 9) {
            const int tb = 1 << (t - 5);
            bool ctrl = (lane >> c) & 1;
#pragma unroll
            for (int r0 = 0; r0 < 16; r0++)
                if (!(r0 & tb)) {
                    const int r1 = r0 | tb;
                    u64 t0 = sr[r0], t1 = si[r0];
                    sr[r0] = ctrl ? sr[r1] : sr[r0];
                    si[r0] = ctrl ? si[r1] : si[r0];
                    sr[r1] = ctrl ? t0 : sr[r1];
                    si[r1] = ctrl ? t1 : si[r1];
                }
        } else {  // t == 9
            bool ctrl = (lane >> c) & 1;
#pragma unroll
            for (int r = 0; r < 16; r++) {
                u64 rr = rot32(sr[r]), ri = rot32(si[r]);
                sr[r] = ctrl ? rr : sr[r];
                si[r] = ctrl ? ri : si[r];
            }
        }
    }
#pragma unroll
    for (int c = 5; c <= 8; c++) {
        const int t = c + R;
        if (t <= 8) {
            const int cb = 1 << (c - 5), tb = 1 << (t - 5);
#pragma unroll
            for (int r0 = 0; r0 < 16; r0++)
                if ((r0 & cb) && !(r0 & tb)) {
                    const int r1 = r0 | tb;
                    u64 tmp = sr[r0]; sr[r0] = sr[r1]; sr[r1] = tmp;
                    tmp = si[r0]; si[r0] = si[r1]; si[r1] = tmp;
                }
        } else if (t == 9) {
            const int cb = 1 << (c - 5);
#pragma unroll
            for (int r = 0; r < 16; r++)
                if (r & cb) {
                    sr[r] = rot32(sr[r]);
                    si[r] = rot32(si[r]);
                }
        }
    }
#pragma unroll
    for (int r = 0; r < 16; r++) {
        const unsigned mlo = ring_mlo<R>(r);
        const unsigned mhi = mlo ^ (1u << (R - 1));
        {
            unsigned lo = (unsigned)sr[r], hi = (unsigned)(sr[r] >> 32);
            if (mlo) lo = __shfl_xor_sync(FULLM, lo, mlo);
            hi = __shfl_xor_sync(FULLM, hi, mhi);
            sr[r] = (u64)lo | ((u64)hi << 32);
        }
        {
            unsigned lo = (unsigned)si[r], hi = (unsigned)(si[r] >> 32);
            if (mlo) lo = __shfl_xor_sync(FULLM, lo, mlo);
            hi = __shfl_xor_sync(FULLM, hi, mhi);
            si[r] = (u64)lo | ((u64)hi << 32);
        }
    }
}

__global__ __launch_bounds__(128, 5) void fused_kernel(
    const float* __restrict__ x, const float* __restrict__ Wp,
    const float* __restrict__ w, const float* __restrict__ Wout,
    const float* __restrict__ bout, float* __restrict__ out, int B) {
    // layer-0 full SU(2) gates + RY(theta) coefficients for layers 1..5
    __shared__ float4 rot0[NQ];
    __shared__ float2 sry[5 * NQ];
    const int tid = threadIdx.x;
    if (tid < DEPTH * NQ) {
        float theta = w[tid * 3 + 1];
        float c, s;
        sincosf(0.5f * theta, &s, &c);
        if (tid < NQ) {
            float phi = w[tid * 3 + 0], omega = w[tid * 3 + 2];
            float sp, cp, sm, cm;
            sincosf(-0.5f * (phi + omega), &sp, &cp);
            sincosf(-0.5f * (phi - omega), &sm, &cm);
            rot0[tid] = make_float4(cp * c, sp * c, -cm * s, sm * s);
        } else {
            sry[tid - NQ] = make_float2(c, s);
        }
    }
    __syncthreads();

    const int warp = tid >> 5, lane = tid & 31;
    const int b = blockIdx.x * 4 + warp;
    if (b >= B) return;

    // ---- projection -> per-lane half-angle trig ----
    float myc = 0.f, mys = 0.f;
    {
        const float4* xv = (const float4*)(x + (size_t)b * NF);
        float acc[NQ];
#pragma unroll
        for (int q = 0; q < NQ; q++) acc[q] = 0.f;
#pragma unroll
        for (int it = 0; it < 8; it++) {
            float4 xx = xv[it * 32 + lane];
#pragma unroll
            for (int q = 0; q < NQ; q++) {
                float4 ww = __ldg(&((const float4*)(Wp + q * NF))[it * 32 + lane]);
                acc[q] += xx.x * ww.x + xx.y * ww.y + xx.z * ww.z + xx.w * ww.w;
            }
        }
#pragma unroll
        for (int off = 16; off > 0; off >>= 1)
#pragma unroll
            for (int q = 0; q < NQ; q++) acc[q] += __shfl_xor_sync(FULLM, acc[q], off);
        if (lane < NQ) {
            float v = acc[0];
#pragma unroll
            for (int q = 1; q < NQ; q++)
                if (lane == q) v = acc[q];
            float half = tanhf(v) * 0.78539816339744831f;
            sincosf(half, &mys, &myc);
        }
    }

    // ---- init: RY product state with FULL layer-0 Rot folded in ----
    float plr, pli;
    {
        plr = 1.f; pli = 0.f;
#pragma unroll
        for (int q = 0; q < 5; q++) {
            float cq = __shfl_sync(FULLM, myc, q);
            float sq = __shfl_sync(FULLM, mys, q);
            float4 G = rot0[q];
            bool bq = (lane >> q) & 1;
            float wr = bq ? (-G.z * cq + G.x * sq) : (G.x * cq + G.z * sq);
            float wi = bq ? (G.w * cq - G.y * sq) : (G.y * cq + G.w * sq);
            float nr = plr * wr - pli * wi;
            float ni = plr * wi + pli * wr;
            plr = nr; pli = ni;
        }
    }
    u64 sr[16], si[16];
    {
        float ar2[4], ai2[4], br2[4], bi2[4];
        {
            float c5 = __shfl_sync(FULLM, myc, 5), s5 = __shfl_sync(FULLM, mys, 5);
            float c6 = __shfl_sync(FULLM, myc, 6), s6 = __shfl_sync(FULLM, mys, 6);
            float c7 = __shfl_sync(FULLM, myc, 7), s7 = __shfl_sync(FULLM, mys, 7);
            float c8 = __shfl_sync(FULLM, myc, 8), s8 = __shfl_sync(FULLM, mys, 8);
            float4 G5 = rot0[5], G6 = rot0[6], G7 = rot0[7], G8 = rot0[8];
            float v5r[2], v5i[2], v6r[2], v6i[2], v7r[2], v7i[2], v8r[2], v8i[2];
            v5r[0] = G5.x * c5 + G5.z * s5; v5i[0] = G5.y * c5 + G5.w * s5;
            v5r[1] = -G5.z * c5 + G5.x * s5; v5i[1] = G5.w * c5 - G5.y * s5;
            v6r[0] = G6.x * c6 + G6.z * s6; v6i[0] = G6.y * c6 + G6.w * s6;
            v6r[1] = -G6.z * c6 + G6.x * s6; v6i[1] = G6.w * c6 - G6.y * s6;
            v7r[0] = G7.x * c7 + G7.z * s7; v7i[0] = G7.y * c7 + G7.w * s7;
            v7r[1] = -G7.z * c7 + G7.x * s7; v7i[1] = G7.w * c7 - G7.y * s7;
            v8r[0] = G8.x * c8 + G8.z * s8; v8i[0] = G8.y * c8 + G8.w * s8;
            v8r[1] = -G8.z * c8 + G8.x * s8; v8i[1] = G8.w * c8 - G8.y * s8;
#pragma unroll
            for (int k = 0; k < 4; k++) {
                int b5 = k & 1, b6 = (k >> 1) & 1;
                ar2[k] = v5r[b5] * v6r[b6] - v5i[b5] * v6i[b6];
                ai2[k] = v5r[b5] * v6i[b6] + v5i[b5] * v6r[b6];
                br2[k] = v7r[b5] * v8r[b6] - v7i[b5] * v8i[b6];
                bi2[k] = v7r[b5] * v8i[b6] + v7i[b5] * v8r[b6];
            }
        }
        float c9 = __shfl_sync(FULLM, myc, 9), s9 = __shfl_sync(FULLM, mys, 9);
        float4 G9 = rot0[9];
        u64 V9r = pk(G9.x * c9 + G9.z * s9, -G9.z * c9 + G9.x * s9);
        u64 V9i = pk(G9.y * c9 + G9.w * s9, G9.w * c9 - G9.y * s9);
#pragma unroll
        for (int r = 0; r < 16; r++) {
            float lr = ar2[r & 3], li = ai2[r & 3];
            float hr = br2[r >> 2], hi = bi2[r >> 2];
            float rpr = lr * hr - li * hi;
            float rpi = lr * hi + li * hr;
            float baser = plr * rpr - pli * rpi;
            float basei = plr * rpi + pli * rpr;
            u64 br_ = dup2(baser), bi_ = dup2(basei);
            sr[r] = fma2(br_, V9r, mul2(neg2(bi_), V9i));
            si[r] = fma2(br_, V9i, mul2(bi_, V9r));
        }
    }

    // ---- ring 1, then layers 1..5: [diag T_l] [RY gates]; rings 2..5 between ----
    cnot_layer<1>(sr, si, lane);
#pragma unroll 1
    for (int l = 1; l < DEPTH; l++) {
        // transition diagonal T_l
        {
            const float4* dtab = &g_diag[(l - 1) * 512];
#pragma unroll
            for (int r = 0; r < 16; r++) {
                float4 d = __ldg(&dtab[r * 32 + lane]);
                u64 drk = pk(d.x, d.y), dik = pk(d.z, d.w);
                u64 mr = sr[r], mi = si[r];
                sr[r] = sub2(mul2(drk, mr), mul2(dik, mi));
                si[r] = fma2(drk, mi, mul2(dik, mr));
            }
        }
        // RY lane gates q0..q4
#pragma unroll
        for (int q = 0; q < 5; q++) {
            float2 cs = sry[(l - 1) * NQ + q];
            bool hb = (lane >> q) & 1;
            u64 C = dup2(cs.x), S = dup2(hb ? cs.y : -cs.y);
#pragma unroll
            for (int r = 0; r < 16; r++) {
                u64 pr_ = __shfl_xor_sync(FULLM, sr[r], 1 << q);
                u64 pi_ = __shfl_xor_sync(FULLM, si[r], 1 << q);
                sr[r] = fma2(C, sr[r], mul2(S, pr_));
                si[r] = fma2(C, si[r], mul2(S, pi_));
            }
        }
        // RY reg gates q5..q8
#pragma unroll
        for (int q = 5; q < 9; q++) {
            float2 cs = sry[(l - 1) * NQ + q];
            u64 C = dup2(cs.x), S = dup2(cs.y), Sn = dup2(-cs.y);
            const int jb = 1 << (q - 5);
#pragma unroll
            for (int r0 = 0; r0 < 16; r0++)
                if (!(r0 & jb)) {
                    const int r1 = r0 | jb;
                    u64 a0r = sr[r0], a0i = si[r0];
                    u64 a1r = sr[r1], a1i = si[r1];
                    sr[r0] = fma2(C, a0r, mul2(Sn, a1r));
                    si[r0] = fma2(C, a0i, mul2(Sn, a1i));
                    sr[r1] = fma2(C, a1r, mul2(S, a0r));
                    si[r1] = fma2(C, a1i, mul2(S, a0i));
                }
        }
        // RY half gate q9
        {
            float2 cs = sry[(l - 1) * NQ + 9];
            u64 C = dup2(cs.x), Spk = pk(-cs.y, cs.y);
#pragma unroll
            for (int r = 0; r < 16; r++) {
                u64 tr = rot32(sr[r]), ti = rot32(si[r]);
                sr[r] = fma2(C, sr[r], mul2(Spk, tr));
                si[r] = fma2(C, si[r], mul2(Spk, ti));
            }
        }
        switch (l) {
            case 1: cnot_layer<2>(sr, si, lane); break;
            case 2: cnot_layer<3>(sr, si, lane); break;
            case 3: cnot_layer<4>(sr, si, lane); break;
            case 4: cnot_layer<5>(sr, si, lane); break;
            default: break;
        }
    }

    // ---- Z expvals with R=6 ring folded in as GF(2) parity masks ----
    u64 A0 = 0ULL, A1 = 0ULL, A2 = 0ULL, A4 = 0ULL, A8 = 0ULL;
#pragma unroll
    for (int r = 0; r < 16; r++) {
        u64 p = fma2(sr[r], sr[r], mul2(si[r], si[r]));
        u64 np = neg2(p);
        A0 = add2(A0, p);
        A1 = add2(A1, (r & 1) ? np : p);
        A2 = add2(A2, (r & 2) ? np : p);
        A4 = add2(A4, (r & 4) ? np : p);
        A8 = add2(A8, (r & 8) ? np : p);
    }
    u64 E[5];
    {
        float lo, hi;
        float e0, e1, e2, e3, e4, e5, e6, e7, e8, e9;
        unpk(A0, lo, hi);
        e0 = lsgn(lane, 0x11, lo + hi);
        e9 = lsgn(lane, 0x08, lo - hi);
        unpk(A1, lo, hi);
        e1 = lsgn(lane, 0x02, lo + hi);
        e5 = lsgn(lane, 0x08, lo - hi);
        unpk(A2, lo, hi);
        e2 = lsgn(lane, 0x05, lo + hi);
        e6 = lsgn(lane, 0x01, lo + hi);
        unpk(A4, lo, hi);
        e3 = lsgn(lane, 0x0A, lo + hi);
        e7 = lsgn(lane, 0x02, lo + hi);
        unpk(A8, lo, hi);
        e4 = lsgn(lane, 0x14, lo + hi);
        e8 = lsgn(lane, 0x04, lo + hi);
        E[0] = pk(e0, e1); E[1] = pk(e2, e3); E[2] = pk(e4, e5);
        E[3] = pk(e6, e7); E[4] = pk(e8, e9);
    }
#pragma unroll
    for (int off = 16; off > 0; off >>= 1)
#pragma unroll
        for (int k = 0; k < 5; k++)
            E[k] = add2(E[k], __shfl_xor_sync(FULLM, E[k], off));

    // ---- linear head ----
    if (lane < NC) {
        float e[NQ];
#pragma unroll
        for (int k = 0; k < 5; k++) unpk(E[k], e[2 * k], e[2 * k + 1]);
        float o = __ldg(&bout[lane]);
#pragma unroll
        for (int q = 0; q < NQ; q++) o += e[q] * __ldg(&Wout[lane * NQ + q]);
        out[(size_t)b * NC + lane] = o;
    }
}

extern "C" void kernel_launch(void* const* d_in, const int* in_sizes, int n_in,
                              void* d_out, int out_size) {
    const float* x = (const float*)d_in[0];
    const float* W_proj = (const float*)d_in[1];
    const float* weights = (const float*)d_in[2];
    const float* W_out = (const float*)d_in[3];
    const float* b_out = (const float*)d_in[4];
    float* out = (float*)d_out;

    int B = in_sizes[0] / NF;
    int nblk = (B + 3) / 4;

    build_diag<<<5, 512>>>(weights);
    fused_kernel<<<nblk, 128>>>(x, W_proj, weights, W_out, b_out, out, B);
}